// round 1
// baseline (speedup 1.0000x reference)
#include <cuda_runtime.h>

// Problem dims (fixed by dataset)
#define BD   4        // batch
#define SD   2048     // seq
#define DD   4096     // in features
#define OD   4096     // out features
#define ED   8        // experts
#define RD   8        // rank
#define MD   (BD*SD)  // 8192 rows
#define NER  (ED*RD)  // 64
#define KTOT (DD+NER) // augmented K: 4160
#define SCALING 2.0f  // 16/8

// Scratch (device globals — no allocation allowed)
__device__ float g_part[BD * 8 * DD];   // partial column sums (8 S-chunks)
__device__ float g_weights[BD * ED];    // SCALING * softmax(router)
__device__ float g_hw[MD * NER];        // SCALING * w[b,e] * (x @ lora_A^T)

// ---------------------------------------------------------------------------
// K1: partial column sums of x over S (for the router mean-pool).
// grid (DD/256, 8, BD), 256 threads. Coalesced over d.
// ---------------------------------------------------------------------------
__global__ void k_colsum(const float* __restrict__ x) {
    int d  = blockIdx.x * 256 + threadIdx.x;
    int sc = blockIdx.y;   // which 256-row S chunk
    int b  = blockIdx.z;
    const float* p = x + ((size_t)b * SD + (size_t)sc * 256) * DD + d;
    float s0 = 0.f, s1 = 0.f, s2 = 0.f, s3 = 0.f;
    #pragma unroll 16
    for (int s = 0; s < 256; s += 4) {
        s0 += p[(size_t)(s + 0) * DD];
        s1 += p[(size_t)(s + 1) * DD];
        s2 += p[(size_t)(s + 2) * DD];
        s3 += p[(size_t)(s + 3) * DD];
    }
    g_part[((size_t)b * 8 + sc) * DD + d] = (s0 + s1) + (s2 + s3);
}

// ---------------------------------------------------------------------------
// K2: router logits + softmax. One block, 256 threads (8 warps).
// logits[b,e] = mean_s(x)[b,:] . router_W[e,:] + router_b[e]
// g_weights = SCALING * softmax(logits)
// ---------------------------------------------------------------------------
__global__ void k_router(const float* __restrict__ rW, const float* __restrict__ rb) {
    __shared__ float logits[BD * ED];
    int warp = threadIdx.x >> 5, lane = threadIdx.x & 31;
    for (int pair = warp; pair < BD * ED; pair += 8) {
        int b = pair >> 3, e = pair & 7;
        float acc = 0.f;
        for (int d = lane; d < DD; d += 32) {
            float cs = 0.f;
            #pragma unroll
            for (int c = 0; c < 8; c++) cs += g_part[((size_t)b * 8 + c) * DD + d];
            acc += cs * rW[(size_t)e * DD + d];
        }
        #pragma unroll
        for (int o = 16; o > 0; o >>= 1) acc += __shfl_xor_sync(0xffffffffu, acc, o);
        if (lane == 0) logits[pair] = acc * (1.0f / (float)SD) + rb[e];
    }
    __syncthreads();
    if (threadIdx.x < BD) {
        int b = threadIdx.x;
        float mx = -1e30f;
        #pragma unroll
        for (int e = 0; e < ED; e++) mx = fmaxf(mx, logits[b * ED + e]);
        float w[ED], sum = 0.f;
        #pragma unroll
        for (int e = 0; e < ED; e++) { w[e] = expf(logits[b * ED + e] - mx); sum += w[e]; }
        float inv = SCALING / sum;
        #pragma unroll
        for (int e = 0; e < ED; e++) g_weights[b * ED + e] = w[e] * inv;
    }
}

// ---------------------------------------------------------------------------
// K3: hw[m, er] = SCALING * w[b, er/8] * sum_d x[m,d] * lora_A[er, d]
// lora_A[E,R,D] is exactly a row-major [64, D] matrix over (e*R+r).
// GEMM M=8192 N=64 K=4096. Tile 64x64, 256 thr, 4x4 micro, K-chunk 32.
// ---------------------------------------------------------------------------
__global__ __launch_bounds__(256) void k_hw(const float* __restrict__ x,
                                            const float* __restrict__ loraA) {
    __shared__ __align__(16) float xs[32][68];  // [k][row]
    __shared__ __align__(16) float as[32][68];  // [k][er]
    int tid = threadIdx.x;
    int rowBase = blockIdx.x * 64;
    int tx = tid & 15, ty = tid >> 4;
    float acc[4][4] = {};
    for (int k0 = 0; k0 < DD; k0 += 32) {
        #pragma unroll
        for (int p = 0; p < 8; p++) {
            int lin = tid + p * 256;
            int r = lin >> 5, k = lin & 31;
            xs[k][r] = x[(size_t)(rowBase + r) * DD + k0 + k];
            as[k][r] = loraA[(size_t)r * DD + k0 + k];
        }
        __syncthreads();
        #pragma unroll
        for (int kk = 0; kk < 32; kk++) {
            float4 xr = *(const float4*)&xs[kk][ty * 4];
            float4 ar = *(const float4*)&as[kk][tx * 4];
            float xv[4] = {xr.x, xr.y, xr.z, xr.w};
            float av[4] = {ar.x, ar.y, ar.z, ar.w};
            #pragma unroll
            for (int i = 0; i < 4; i++)
                #pragma unroll
                for (int j = 0; j < 4; j++)
                    acc[i][j] += xv[i] * av[j];
        }
        __syncthreads();
    }
    int b = rowBase / SD;   // all 64 rows share batch index (S % 64 == 0)
    #pragma unroll
    for (int j = 0; j < 4; j++) {
        int er = tx * 4 + j;
        float sc = g_weights[b * ED + (er >> 3)];
        #pragma unroll
        for (int i = 0; i < 4; i++)
            g_hw[(size_t)(rowBase + ty * 4 + i) * NER + er] = acc[i][j] * sc;
    }
}

// ---------------------------------------------------------------------------
// K4: fused main GEMM with augmented K:
//   out[m,o] = sum_{k<D} x[m,k] W_base[o,k]
//            + sum_{er}  hw[m,er] * lora_B[er/8, o, er%8]
//            + b_base[o]
// Tile 128x128, 256 thr, 8x8 micro, K-chunk 8, register prefetch.
// ---------------------------------------------------------------------------
__global__ __launch_bounds__(256, 2) void k_main(const float* __restrict__ x,
                                                 const float* __restrict__ Wb,
                                                 const float* __restrict__ bb,
                                                 const float* __restrict__ loraB,
                                                 float* __restrict__ out) {
    __shared__ __align__(16) float As[8][132];  // [k][m] transposed
    __shared__ __align__(16) float Bs[8][132];  // [k][n] transposed
    int tid = threadIdx.x;
    int mBase = blockIdx.y * 128;
    int nBase = blockIdx.x * 128;
    int tx = tid & 15, ty = tid >> 4;
    int lr = tid >> 1;              // 0..127: tile row (A) / tile col (B)
    int lk = (tid & 1) * 4;         // 0 or 4 within K-chunk
    float acc[8][8] = {};

    auto loadA = [&](int k0) -> float4 {
        if (k0 < DD)
            return *(const float4*)(x + (size_t)(mBase + lr) * DD + k0 + lk);
        return *(const float4*)(g_hw + (size_t)(mBase + lr) * NER + (k0 - DD) + lk);
    };
    auto loadB = [&](int k0) -> float4 {
        if (k0 < DD)
            return *(const float4*)(Wb + (size_t)(nBase + lr) * DD + k0 + lk);
        int er = k0 - DD + lk;      // er % 8 in {0,4}: float4 stays inside one expert
        return *(const float4*)(loraB + ((size_t)(er >> 3) * OD + nBase + lr) * RD + (er & 7));
    };

    float4 an = loadA(0), bn = loadB(0);
    for (int k0 = 0; k0 < KTOT; k0 += 8) {
        As[lk + 0][lr] = an.x; As[lk + 1][lr] = an.y;
        As[lk + 2][lr] = an.z; As[lk + 3][lr] = an.w;
        Bs[lk + 0][lr] = bn.x; Bs[lk + 1][lr] = bn.y;
        Bs[lk + 2][lr] = bn.z; Bs[lk + 3][lr] = bn.w;
        __syncthreads();
        if (k0 + 8 < KTOT) { an = loadA(k0 + 8); bn = loadB(k0 + 8); }
        #pragma unroll
        for (int kk = 0; kk < 8; kk++) {
            float4 a0 = *(const float4*)&As[kk][ty * 8];
            float4 a1 = *(const float4*)&As[kk][ty * 8 + 4];
            float4 b0 = *(const float4*)&Bs[kk][tx * 8];
            float4 b1 = *(const float4*)&Bs[kk][tx * 8 + 4];
            float av[8] = {a0.x, a0.y, a0.z, a0.w, a1.x, a1.y, a1.z, a1.w};
            float bv[8] = {b0.x, b0.y, b0.z, b0.w, b1.x, b1.y, b1.z, b1.w};
            #pragma unroll
            for (int i = 0; i < 8; i++)
                #pragma unroll
                for (int j = 0; j < 8; j++)
                    acc[i][j] += av[i] * bv[j];
        }
        __syncthreads();
    }

    float bbv[8];
    #pragma unroll
    for (int j = 0; j < 8; j++) bbv[j] = bb[nBase + tx * 8 + j];
    #pragma unroll
    for (int i = 0; i < 8; i++) {
        size_t m = (size_t)mBase + ty * 8 + i;
        float* orow = out + m * OD + nBase + tx * 8;
        float4 v0 = make_float4(acc[i][0] + bbv[0], acc[i][1] + bbv[1],
                                acc[i][2] + bbv[2], acc[i][3] + bbv[3]);
        float4 v1 = make_float4(acc[i][4] + bbv[4], acc[i][5] + bbv[5],
                                acc[i][6] + bbv[6], acc[i][7] + bbv[7]);
        *(float4*)orow = v0;
        *(float4*)(orow + 4) = v1;
    }
}

// ---------------------------------------------------------------------------
extern "C" void kernel_launch(void* const* d_in, const int* in_sizes, int n_in,
                              void* d_out, int out_size) {
    const float* x   = (const float*)d_in[0];  // [B,S,D]
    const float* Wb  = (const float*)d_in[1];  // [O,D]
    const float* bbv = (const float*)d_in[2];  // [O]
    const float* lA  = (const float*)d_in[3];  // [E,R,D]
    const float* lB  = (const float*)d_in[4];  // [E,O,R]
    const float* rW  = (const float*)d_in[5];  // [E,D]
    const float* rb  = (const float*)d_in[6];  // [E]
    float* out = (float*)d_out;                // [B,S,O] fp32

    k_colsum<<<dim3(DD / 256, 8, BD), 256>>>(x);
    k_router<<<1, 256>>>(rW, rb);
    k_hw<<<MD / 64, 256>>>(x, lA);
    k_main<<<dim3(OD / 128, MD / 128), 256>>>(x, Wb, bbv, lB, out);
}

// round 3
// speedup vs baseline: 2.8206x; 2.8206x over previous
#include <cuda_runtime.h>
#include <cstdint>

// Problem dims (fixed by dataset)
#define BD   4
#define SD   2048
#define DD   4096
#define OD   4096
#define ED   8
#define RD   8
#define MD   (BD*SD)   // 8192
#define NER  64        // E*R
#define KTOT (DD+NER)  // 4160
#define SCALING 2.0f

// Main GEMM tiling (mma.sync tf32)
#define TM 128
#define TN 128
#define KC 32                 // fp32 elems per K-chunk = 128 bytes per row
#define NCHUNK (KTOT/KC)      // 130
#define SMEM_STAGE 32768u     // A(16K) + B(16K)
#define SMEM_BYTES (2u * SMEM_STAGE)

// Scratch
__device__ float g_part[BD * 8 * DD];
__device__ float g_weights[BD * ED];
__device__ float g_hw[MD * NER];

// ---------------- helpers ----------------
__device__ __forceinline__ uint32_t smem_u32(const void* p) {
    uint32_t a;
    asm("{ .reg .u64 t; cvta.to.shared.u64 t, %1; cvt.u32.u64 %0, t; }" : "=r"(a) : "l"(p));
    return a;
}
__device__ __forceinline__ uint32_t f2tf32(float f) {   // round-to-nearest tf32
    uint32_t u;
    asm("cvt.rna.tf32.f32 %0, %1;" : "=r"(u) : "f"(f));
    return u;
}
#define SW128(o) ((o) ^ (((o) >> 3) & 0x70))

__device__ __forceinline__ void ldsm4(uint32_t* r, uint32_t addr) {
    asm volatile("ldmatrix.sync.aligned.m8n8.x4.shared.b16 {%0,%1,%2,%3}, [%4];"
                 : "=r"(r[0]), "=r"(r[1]), "=r"(r[2]), "=r"(r[3]) : "r"(addr));
}
__device__ __forceinline__ void mma8(float* d, const uint32_t* a, uint32_t b0, uint32_t b1) {
    asm volatile("mma.sync.aligned.m16n8k8.row.col.f32.tf32.tf32.f32 "
                 "{%0,%1,%2,%3}, {%4,%5,%6,%7}, {%8,%9}, {%0,%1,%2,%3};"
                 : "+f"(d[0]), "+f"(d[1]), "+f"(d[2]), "+f"(d[3])
                 : "r"(a[0]), "r"(a[1]), "r"(a[2]), "r"(a[3]), "r"(b0), "r"(b1));
}

// ---------------------------------------------------------------------------
// K1: partial column sums of x over S (router mean-pool input)
// ---------------------------------------------------------------------------
__global__ void k_colsum(const float* __restrict__ x) {
    int d  = blockIdx.x * 256 + threadIdx.x;
    int sc = blockIdx.y;
    int b  = blockIdx.z;
    const float* p = x + ((size_t)b * SD + (size_t)sc * 256) * DD + d;
    float s0 = 0.f, s1 = 0.f, s2 = 0.f, s3 = 0.f;
    #pragma unroll 16
    for (int s = 0; s < 256; s += 4) {
        s0 += p[(size_t)(s + 0) * DD];
        s1 += p[(size_t)(s + 1) * DD];
        s2 += p[(size_t)(s + 2) * DD];
        s3 += p[(size_t)(s + 3) * DD];
    }
    g_part[((size_t)b * 8 + sc) * DD + d] = (s0 + s1) + (s2 + s3);
}

// ---------------------------------------------------------------------------
// K2: router logits + softmax -> g_weights = SCALING * softmax
// ---------------------------------------------------------------------------
__global__ void k_router(const float* __restrict__ rW, const float* __restrict__ rb) {
    __shared__ float logits[BD * ED];
    int warp = threadIdx.x >> 5, lane = threadIdx.x & 31;
    for (int pair = warp; pair < BD * ED; pair += 8) {
        int b = pair >> 3, e = pair & 7;
        float acc = 0.f;
        for (int d = lane; d < DD; d += 32) {
            float cs = 0.f;
            #pragma unroll
            for (int c = 0; c < 8; c++) cs += g_part[((size_t)b * 8 + c) * DD + d];
            acc += cs * rW[(size_t)e * DD + d];
        }
        #pragma unroll
        for (int o = 16; o > 0; o >>= 1) acc += __shfl_xor_sync(0xffffffffu, acc, o);
        if (lane == 0) logits[pair] = acc * (1.0f / (float)SD) + rb[e];
    }
    __syncthreads();
    if (threadIdx.x < BD) {
        int b = threadIdx.x;
        float mx = -1e30f;
        #pragma unroll
        for (int e = 0; e < ED; e++) mx = fmaxf(mx, logits[b * ED + e]);
        float w[ED], sum = 0.f;
        #pragma unroll
        for (int e = 0; e < ED; e++) { w[e] = expf(logits[b * ED + e] - mx); sum += w[e]; }
        float inv = SCALING / sum;
        #pragma unroll
        for (int e = 0; e < ED; e++) g_weights[b * ED + e] = w[e] * inv;
    }
}

// ---------------------------------------------------------------------------
// K3: hw[m, er] = SCALING * w[b, er/8] * (x @ lora_A^T)   (M=8192,N=64,K=4096)
// ---------------------------------------------------------------------------
__global__ __launch_bounds__(256) void k_hw(const float* __restrict__ x,
                                            const float* __restrict__ loraA) {
    __shared__ __align__(16) float xs[32][68];
    __shared__ __align__(16) float as[32][68];
    int tid = threadIdx.x;
    int rowBase = blockIdx.x * 64;
    int tx = tid & 15, ty = tid >> 4;
    float acc[4][4] = {};
    for (int k0 = 0; k0 < DD; k0 += 32) {
        #pragma unroll
        for (int p = 0; p < 8; p++) {
            int lin = tid + p * 256;
            int r = lin >> 5, k = lin & 31;
            xs[k][r] = x[(size_t)(rowBase + r) * DD + k0 + k];
            as[k][r] = loraA[(size_t)r * DD + k0 + k];
        }
        __syncthreads();
        #pragma unroll
        for (int kk = 0; kk < 32; kk++) {
            float4 xr = *(const float4*)&xs[kk][ty * 4];
            float4 ar = *(const float4*)&as[kk][tx * 4];
            float xv[4] = {xr.x, xr.y, xr.z, xr.w};
            float av[4] = {ar.x, ar.y, ar.z, ar.w};
            #pragma unroll
            for (int i = 0; i < 4; i++)
                #pragma unroll
                for (int j = 0; j < 4; j++)
                    acc[i][j] += xv[i] * av[j];
        }
        __syncthreads();
    }
    int b = rowBase / SD;
    #pragma unroll
    for (int j = 0; j < 4; j++) {
        int er = tx * 4 + j;
        float sc = g_weights[b * ED + (er >> 3)];
        #pragma unroll
        for (int i = 0; i < 4; i++)
            g_hw[(size_t)(rowBase + ty * 4 + i) * NER + er] = acc[i][j] * sc;
    }
}

// ---------------------------------------------------------------------------
// K4: tf32 mma.sync main GEMM, augmented K, bias epilogue.
//   out[m,n] = sum_{k<D} x[m,k]*Wb[n,k] + sum_{er} hw[m,er]*loraB[er/8,n,er%8] + bb[n]
// Block 128x128, 8 warps (4x2), warp tile 32x64, K-chunk 32, double-buffered.
// SMEM per stage: A[128 rows][32 k] + B[128 rows][32 k], 128B rows, SW128.
// A row-major over m (k contiguous), B stored [n][k] (k contiguous).
// ---------------------------------------------------------------------------
__global__ __launch_bounds__(256) void k_main_mma(const float* __restrict__ x,
                                                  const float* __restrict__ Wb,
                                                  const float* __restrict__ bb,
                                                  const float* __restrict__ loraB,
                                                  float* __restrict__ out) {
    extern __shared__ char smem[];
    uint32_t sbase = smem_u32(smem);

    int tid = threadIdx.x, lane = tid & 31, wid = tid >> 5;
    int wm = (wid & 3) * 32;       // warp m-offset in tile
    int wn = (wid >> 2) * 64;      // warp n-offset in tile
    int mBase = blockIdx.y * TM;
    int nBase = blockIdx.x * TN;

    float acc[2][8][4] = {};

    // ldmatrix lane-derived row/byte offsets
    int rA  = wm + (lane & 7) + ((lane >> 3) & 1) * 8;   // + f*16
    int cAb = ((lane >> 4) & 1) * 16;
    int rB  = wn + (lane & 7) + ((lane >> 4) & 1) * 8;   // + g*16
    int cBb = ((lane >> 3) & 1) * 16;

    // staging: thread handles 4 (row, quad) pairs each for A and B
    int sq = tid & 7;              // quad within 128B row
    int sr = tid >> 3;             // base row (add p*32)

    auto ldg_chunk = [&](int k0, float4* pa, float4* pb) {
        int c = 4 * sq;
        #pragma unroll
        for (int p = 0; p < 4; p++) {
            int row = sr + p * 32;
            if (k0 < DD) {
                pa[p] = *(const float4*)(x  + (size_t)(mBase + row) * DD + k0 + c);
                pb[p] = *(const float4*)(Wb + (size_t)(nBase + row) * DD + k0 + c);
            } else {
                pa[p] = *(const float4*)(g_hw + (size_t)(mBase + row) * NER + (k0 - DD) + c);
                int er = (k0 - DD) + c;   // er&7 in {0,4}: float4 inside one expert
                pb[p] = *(const float4*)(loraB + ((size_t)(er >> 3) * OD + nBase + row) * RD + (er & 7));
            }
        }
    };

    float4 pa[4], pb[4];
    ldg_chunk(0, pa, pb);

    for (int i = 0; i < NCHUNK; i++) {
        uint32_t offA = (i & 1) ? SMEM_STAGE : 0u;
        uint32_t offB = offA + 16384u;

        // stage chunk i (cvt to tf32 here: RN rounding, keeps bias tiny)
        #pragma unroll
        for (int p = 0; p < 4; p++) {
            int row = sr + p * 32;
            uint32_t so = SW128((uint32_t)(row * 128 + sq * 16));
            uint4 ta = { f2tf32(pa[p].x), f2tf32(pa[p].y), f2tf32(pa[p].z), f2tf32(pa[p].w) };
            uint4 tb = { f2tf32(pb[p].x), f2tf32(pb[p].y), f2tf32(pb[p].z), f2tf32(pb[p].w) };
            *(uint4*)(smem + offA + so) = ta;
            *(uint4*)(smem + offB + so) = tb;
        }
        __syncthreads();

        if (i + 1 < NCHUNK) ldg_chunk((i + 1) * KC, pa, pb);

        uint32_t aB = sbase + offA, bB = sbase + offB;
        #pragma unroll
        for (int ks = 0; ks < 4; ks++) {
            uint32_t af[2][4];
            #pragma unroll
            for (int f = 0; f < 2; f++)
                ldsm4(af[f], aB + SW128((uint32_t)((rA + f * 16) * 128 + ks * 32 + cAb)));
            uint32_t bf[4][4];
            #pragma unroll
            for (int g = 0; g < 4; g++)
                ldsm4(bf[g], bB + SW128((uint32_t)((rB + g * 16) * 128 + ks * 32 + cBb)));
            #pragma unroll
            for (int f = 0; f < 2; f++)
                #pragma unroll
                for (int g = 0; g < 4; g++) {
                    mma8(acc[f][2 * g],     af[f], bf[g][0], bf[g][1]);
                    mma8(acc[f][2 * g + 1], af[f], bf[g][2], bf[g][3]);
                }
        }
        __syncthreads();
    }

    // Epilogue: c0,c1 at (m, n..n+1); c2,c3 at (m+8, n..n+1); add bias
    #pragma unroll
    for (int f = 0; f < 2; f++) {
        int m0 = mBase + wm + f * 16 + (lane >> 2);
        #pragma unroll
        for (int g = 0; g < 8; g++) {
            int n = nBase + wn + g * 8 + 2 * (lane & 3);
            float b0 = bb[n], b1 = bb[n + 1];
            float2 v0 = { acc[f][g][0] + b0, acc[f][g][1] + b1 };
            float2 v1 = { acc[f][g][2] + b0, acc[f][g][3] + b1 };
            *(float2*)(out + (size_t)m0 * OD + n)       = v0;
            *(float2*)(out + (size_t)(m0 + 8) * OD + n) = v1;
        }
    }
}

// ---------------------------------------------------------------------------
extern "C" void kernel_launch(void* const* d_in, const int* in_sizes, int n_in,
                              void* d_out, int out_size) {
    const float* x   = (const float*)d_in[0];
    const float* Wb  = (const float*)d_in[1];
    const float* bbv = (const float*)d_in[2];
    const float* lA  = (const float*)d_in[3];
    const float* lB  = (const float*)d_in[4];
    const float* rW  = (const float*)d_in[5];
    const float* rb  = (const float*)d_in[6];
    float* out = (float*)d_out;

    cudaFuncSetAttribute(k_main_mma, cudaFuncAttributeMaxDynamicSharedMemorySize, SMEM_BYTES);

    k_colsum<<<dim3(DD / 256, 8, BD), 256>>>(x);
    k_router<<<1, 256>>>(rW, rb);
    k_hw<<<MD / 64, 256>>>(x, lA);
    k_main_mma<<<dim3(OD / TN, MD / TM), 256, SMEM_BYTES>>>(x, Wb, bbv, lB, out);
}